// round 10
// baseline (speedup 1.0000x reference)
#include <cuda_runtime.h>
#include <cuda_fp16.h>
#include <stdint.h>

// ---------------- problem constants ----------------
#define BB 4
#define LL 10000
#define KK 16
#define II 256
#define OO 256
#define MTOT (BB * LL)          // 40000
#define MTILES 625              // 40000 / 64 exactly (no tail)

// ---------------- device scratch ----------------
__device__ __align__(16) __half g_xh[(size_t)BB * LL * II];     // x in fp16
__device__ __align__(16) __half g_maskT[(size_t)KK * OO * II];  // mask transposed: [k][o][i]

// ---------------- helpers ----------------
__device__ __forceinline__ uint32_t smem_to_u32(const void* p) {
    uint32_t a;
    asm("{ .reg .u64 t; cvta.to.shared.u64 t, %1; cvt.u32.u64 %0, t; }"
        : "=r"(a) : "l"(p));
    return a;
}
__device__ __forceinline__ void cp_async16(uint32_t dst, const void* src) {
    asm volatile("cp.async.cg.shared.global [%0], [%1], 16;" :: "r"(dst), "l"(src));
}
#define CP_COMMIT() asm volatile("cp.async.commit_group;" ::: "memory")
#define CP_WAIT1()  asm volatile("cp.async.wait_group 1;" ::: "memory")

__device__ __forceinline__ void ldmx4(uint32_t& r0, uint32_t& r1, uint32_t& r2, uint32_t& r3,
                                      uint32_t addr) {
    asm volatile("ldmatrix.sync.aligned.m8n8.x4.shared.b16 {%0,%1,%2,%3}, [%4];"
                 : "=r"(r0), "=r"(r1), "=r"(r2), "=r"(r3) : "r"(addr));
}
__device__ __forceinline__ void mma16816(float* c, const uint32_t* a, uint32_t b0, uint32_t b1) {
    asm volatile(
        "mma.sync.aligned.m16n8k16.row.col.f32.f16.f16.f32 "
        "{%0,%1,%2,%3}, {%4,%5,%6,%7}, {%8,%9}, {%0,%1,%2,%3};"
        : "+f"(c[0]), "+f"(c[1]), "+f"(c[2]), "+f"(c[3])
        : "r"(a[0]), "r"(a[1]), "r"(a[2]), "r"(a[3]), "r"(b0), "r"(b1));
}

// ---------------- merged prologue ----------------
__global__ void __launch_bounds__(1024)
prologue_kernel(const float* __restrict__ x, const float* __restrict__ mask) {
    if (blockIdx.x < 2500) {
        int t = blockIdx.x * 1024 + threadIdx.x;
        float4 v = ((const float4*)x)[t];
        __half2* dst = ((__half2*)g_xh) + 2 * t;
        dst[0] = __floats2half2_rn(v.x, v.y);
        dst[1] = __floats2half2_rn(v.z, v.w);
    } else {
        __shared__ float ts[32][33];
        int bb  = blockIdx.x - 2500;         // 0..1023
        int k   = bb >> 6;                   // 16 experts
        int rem = bb & 63;
        int i0  = (rem >> 3) * 32;
        int o0  = (rem & 7) * 32;
        int tx  = threadIdx.x & 31;
        int ty  = threadIdx.x >> 5;
        ts[ty][tx] = mask[((size_t)k * II + (i0 + ty)) * OO + o0 + tx];
        __syncthreads();
        g_maskT[((size_t)k * OO + (o0 + ty)) * II + i0 + tx] = __float2half(ts[tx][ty]);
    }
}

// ---------------- main kernel ----------------
// CTA tile: 64 (M) x 128 (N). 2 warps split N, each 64x64 (R8's efficient inner loop).
// Dynamic smem: [0,1024) gather indices; 3 stages of (A 64x128B | B 128x128B) = 24KB.
// 74KB/CTA -> 3 CTAs/SM. Grid (625,2): 40000 = 625*64 exactly, no ragged tail.
#define SM_IDX   0
#define SM_STAGE 1024
#define STAGE_BYTES 24576
#define A_BYTES  8192
#define DYN_SMEM (SM_STAGE + 3 * STAGE_BYTES)   // 74752
#define NTHREADS 64

__device__ __forceinline__ void issue_chunk(int c, uint32_t stage, const int* sIdx,
                                            int n0, int tid) {
    const int kexp  = c >> 2;
    const int ibase = (c & 3) * 64;
    const uint32_t Ab = stage;
    const uint32_t Bb = stage + A_BYTES;
    // A: 64 rows x 128B (512 16B-loads), gathered
#pragma unroll
    for (int j = 0; j < 8; j++) {
        int s   = tid + NTHREADS * j;
        int row = s >> 3, seg = s & 7;
        int li  = row >> 2, b = row & 3;
        int jr  = sIdx[li * 16 + kexp];
        const __half* src = g_xh + ((size_t)(b * LL + jr)) * II + ibase + seg * 8;
        uint32_t off = (uint32_t)(row * 128 + seg * 16);
        cp_async16(Ab + (off ^ ((row & 7) << 4)), src);
    }
    // B: 128 rows (o in [n0, n0+128)) x 128B (1024 16B-loads)
#pragma unroll
    for (int j = 0; j < 16; j++) {
        int s   = tid + NTHREADS * j;
        int row = s >> 3, seg = s & 7;
        const __half* src = g_maskT + ((size_t)(kexp * OO + n0 + row)) * II + ibase + seg * 8;
        uint32_t off = (uint32_t)(row * 128 + seg * 16);
        cp_async16(Bb + (off ^ ((row & 7) << 4)), src);
    }
}

__global__ void __launch_bounds__(NTHREADS, 3)
piconv_mma_kernel(const int* __restrict__ idx,
                  const float* __restrict__ bias,
                  float* __restrict__ out) {
    extern __shared__ char sm[];
    const uint32_t sb = smem_to_u32(sm);
    const int tid    = threadIdx.x;
    const int lane   = tid & 31;
    const int warp_n = tid >> 5;           // 0..1 (64 cols each)
    const int tile   = blockIdx.x;         // M tile (64 rows = 16 l-values)
    const int n0     = blockIdx.y * 128;   // N tile
    const int l0     = tile * 16;

    // Stage gather indices (16 l-values x 16 k) — exact, no clamping needed
    int* sIdx = (int*)(sm + SM_IDX);
#pragma unroll
    for (int e = tid; e < 256; e += NTHREADS) {
        sIdx[e] = idx[(l0 + (e >> 4)) * KK + (e & 15)];
    }
    __syncthreads();

    // 64x64 warp tile: acc[am 0..3][nn 0..7][4] = 128 regs
    float acc[4][8][4];
#pragma unroll
    for (int a = 0; a < 4; a++)
#pragma unroll
        for (int n = 0; n < 8; n++)
#pragma unroll
            for (int q = 0; q < 4; q++) acc[a][n][q] = 0.f;

    issue_chunk(0, sb + SM_STAGE + 0 * STAGE_BYTES, sIdx, n0, tid);
    CP_COMMIT();
    issue_chunk(1, sb + SM_STAGE + 1 * STAGE_BYTES, sIdx, n0, tid);
    CP_COMMIT();

    // Per-lane ldmatrix address invariants
    const int rA        = lane & 15;                      // am adds +16 rows (row&7 invariant)
    const uint32_t aRow = (uint32_t)rA * 128u;
    const uint32_t aPh  = (uint32_t)((rA & 7) << 4);
    const int colAh     = (lane >> 4) * 16;
    const int rBb       = warp_n * 64 + (lane & 7) + ((lane >> 4) << 3);  // nb adds +16 rows
    const uint32_t bPh  = (uint32_t)((lane & 7) << 4);
    const int colBh     = ((lane >> 3) & 1) * 16;

    for (int c = 0; c < 64; c++) {
        CP_WAIT1();
        __syncthreads();

        if (c + 2 < 64)
            issue_chunk(c + 2, sb + SM_STAGE + ((c + 2) % 3) * STAGE_BYTES, sIdx, n0, tid);
        CP_COMMIT();

        const uint32_t Ab = sb + SM_STAGE + (c % 3) * STAGE_BYTES;
        const uint32_t Bb = Ab + A_BYTES;

#pragma unroll
        for (int ks = 0; ks < 4; ks++) {
            uint32_t a[4][4];
            const uint32_t offA = (uint32_t)(ks * 32 + colAh) ^ aPh;
#pragma unroll
            for (int am = 0; am < 4; am++)
                ldmx4(a[am][0], a[am][1], a[am][2], a[am][3],
                      Ab + aRow + (uint32_t)am * 2048u + offA);

            const uint32_t offB = (uint32_t)(ks * 32 + colBh) ^ bPh;
            uint32_t b[4][4];
#pragma unroll
            for (int nb = 0; nb < 4; nb++) {
                const int rB = rBb + nb * 16;
                ldmx4(b[nb][0], b[nb][1], b[nb][2], b[nb][3],
                      Bb + (uint32_t)rB * 128u + offB);
            }
#pragma unroll
            for (int am = 0; am < 4; am++) {
#pragma unroll
                for (int nb = 0; nb < 4; nb++) {
                    mma16816(acc[am][nb * 2 + 0], a[am], b[nb][0], b[nb][1]);
                    mma16816(acc[am][nb * 2 + 1], a[am], b[nb][2], b[nb][3]);
                }
            }
        }
    }

    // ---- Epilogue: bias add + store (row m -> b = m&3, l = m>>2); no tail ----
#pragma unroll
    for (int am = 0; am < 4; am++) {
#pragma unroll
        for (int nn = 0; nn < 8; nn++) {
            const int o = n0 + warp_n * 64 + nn * 8 + (lane & 3) * 2;
            const float2 bz = *(const float2*)&bias[o];
            const int m = tile * 64 + am * 16 + (lane >> 2);
            {
                float2 v;
                v.x = acc[am][nn][0] + bz.x;
                v.y = acc[am][nn][1] + bz.y;
                *(float2*)&out[((size_t)(m & 3) * LL + (m >> 2)) * OO + o] = v;
            }
            const int m2 = m + 8;
            {
                float2 v;
                v.x = acc[am][nn][2] + bz.x;
                v.y = acc[am][nn][3] + bz.y;
                *(float2*)&out[((size_t)(m2 & 3) * LL + (m2 >> 2)) * OO + o] = v;
            }
        }
    }
}

// ---------------- launch ----------------
extern "C" void kernel_launch(void* const* d_in, const int* in_sizes, int n_in,
                              void* d_out, int out_size) {
    const float* x    = (const float*)d_in[0];   // (4, 10000, 256) fp32
    const int*   idx  = (const int*)d_in[1];     // (10000, 16) int32
    const float* mask = (const float*)d_in[2];   // (16, 256, 256) fp32
    const float* bias = (const float*)d_in[3];   // (256,) fp32
    float*       out  = (float*)d_out;           // (4, 10000, 256) fp32

    (void)in_sizes; (void)n_in; (void)out_size;

    static bool attr_set = false;
    if (!attr_set) {
        cudaFuncSetAttribute(piconv_mma_kernel,
                             cudaFuncAttributeMaxDynamicSharedMemorySize, DYN_SMEM);
        attr_set = true;
    }

    prologue_kernel<<<3524, 1024>>>(x, mask);
    piconv_mma_kernel<<<dim3(MTILES, 2), NTHREADS, DYN_SMEM>>>(idx, bias, out);
}